// round 2
// baseline (speedup 1.0000x reference)
#include <cuda_runtime.h>
#include <cuda_bf16.h>
#include <cstdint>

#define N_NODES 40000
#define DIMF    128
#define N_EDGES 640000

// ---- scratch (no allocs allowed) ----
__device__ float g_agg[N_NODES * DIMF];   // neighbor-sum / mean buffer
__device__ float g_cnt[N_NODES];          // in-degree (float)
__device__ float g_h[N_NODES * DIMF];     // layer-1 output

// ---------------------------------------------------------------------------
// zero agg (+ cnt on first layer)
// ---------------------------------------------------------------------------
__global__ void zero_kernel(int zero_cnt) {
    int i = blockIdx.x * blockDim.x + threadIdx.x;
    const int tot4 = N_NODES * DIMF / 4;
    if (i < tot4) reinterpret_cast<float4*>(g_agg)[i] = make_float4(0.f, 0.f, 0.f, 0.f);
    if (zero_cnt && i < N_NODES) g_cnt[i] = 0.f;
}

// ---------------------------------------------------------------------------
// scatter: one warp per edge. Each lane moves one float4 (32 lanes x 16B = 512B row).
// Vector reduction (red.global.add.v4.f32, sm_90+) — no return value.
// edge_index is int32 (JAX x64 disabled downcasts the int64 request).
// ---------------------------------------------------------------------------
__global__ void scatter_kernel(const float* __restrict__ feat,
                               const int* __restrict__ ei,
                               int do_count) {
    int gw   = blockIdx.x * (blockDim.x >> 5) + (threadIdx.x >> 5);
    int lane = threadIdx.x & 31;
    if (gw >= N_EDGES) return;
    int s = ei[gw];
    int d = ei[N_EDGES + gw];
    // defensive: a bad index becomes a skipped edge (visible as rel_err),
    // not an illegal access.
    if ((unsigned)s >= N_NODES || (unsigned)d >= N_NODES) return;

    float4 v = reinterpret_cast<const float4*>(feat + (size_t)s * DIMF)[lane];
    float* p = g_agg + (size_t)d * DIMF + lane * 4;
    asm volatile("red.global.add.v4.f32 [%0], {%1, %2, %3, %4};"
                 :: "l"(p), "f"(v.x), "f"(v.y), "f"(v.z), "f"(v.w)
                 : "memory");
    if (do_count && lane == 0) {
        atomicAdd(&g_cnt[d], 1.0f);
    }
}

// ---------------------------------------------------------------------------
// normalize: agg[n] /= max(cnt[n], 1)
// ---------------------------------------------------------------------------
__global__ void normalize_kernel() {
    int i = blockIdx.x * blockDim.x + threadIdx.x;     // float4 index
    const int tot4 = N_NODES * DIMF / 4;
    if (i >= tot4) return;
    int n = i / (DIMF / 4);
    float inv = 1.0f / fmaxf(g_cnt[n], 1.0f);
    float4 v = reinterpret_cast<float4*>(g_agg)[i];
    v.x *= inv; v.y *= inv; v.z *= inv; v.w *= inv;
    reinterpret_cast<float4*>(g_agg)[i] = v;
}

// ---------------------------------------------------------------------------
// fused SAGE GEMM: out[m][n] = relu( sum_k A0[m][k]*W0[n][k]
//                                  + sum_k A1[m][k]*W1[n][k] + bias[n] )
// NT gemm, M=40000, N=128, K=128 (x2 weight mats). BM=BN=128, BK=16, 256 thr,
// 8x8 register micro-tile per thread.
// ---------------------------------------------------------------------------
#define BM 128
#define BN 128
#define BK 16
#define TM 8
#define TN 8

__global__ __launch_bounds__(256) void gemm_fused_kernel(
        const float* __restrict__ A0, const float* __restrict__ A1,
        const float* __restrict__ W0, const float* __restrict__ W1,
        const float* __restrict__ bias, float* __restrict__ out) {
    __shared__ float As[BK][BM + 4];
    __shared__ float Bs[BK][BN + 4];

    const int tid = threadIdx.x;
    const int m0  = blockIdx.x * BM;
    const int tr  = tid >> 4;     // 0..15
    const int tc  = tid & 15;     // 0..15

    float acc[TM][TN];
#pragma unroll
    for (int i = 0; i < TM; ++i)
#pragma unroll
        for (int j = 0; j < TN; ++j) acc[i][j] = 0.f;

#pragma unroll 1
    for (int w = 0; w < 2; ++w) {
        const float* A = w ? A1 : A0;
        const float* W = w ? W1 : W0;
#pragma unroll 1
        for (int k0 = 0; k0 < DIMF; k0 += BK) {
            // load A tile (BM x BK) transposed into As[kk][m]
#pragma unroll
            for (int i = 0; i < 8; ++i) {
                int e  = tid + i * 256;
                int m  = e >> 4;
                int kk = e & 15;
                int gm = m0 + m;
                As[kk][m] = (gm < N_NODES) ? A[(size_t)gm * DIMF + k0 + kk] : 0.f;
            }
            // load W tile (BN x BK) transposed into Bs[kk][n]
#pragma unroll
            for (int i = 0; i < 8; ++i) {
                int e  = tid + i * 256;
                int n  = e >> 4;
                int kk = e & 15;
                Bs[kk][n] = W[(size_t)n * DIMF + k0 + kk];
            }
            __syncthreads();
#pragma unroll
            for (int k = 0; k < BK; ++k) {
                float a[TM], b[TN];
#pragma unroll
                for (int i = 0; i < TM; ++i) a[i] = As[k][tr * TM + i];
#pragma unroll
                for (int j = 0; j < TN; ++j) b[j] = Bs[k][tc * TN + j];
#pragma unroll
                for (int i = 0; i < TM; ++i)
#pragma unroll
                    for (int j = 0; j < TN; ++j) acc[i][j] += a[i] * b[j];
            }
            __syncthreads();
        }
    }

    // epilogue: + bias, relu
#pragma unroll
    for (int i = 0; i < TM; ++i) {
        int gm = m0 + tr * TM + i;
        if (gm >= N_NODES) continue;
#pragma unroll
        for (int j = 0; j < TN; j += 4) {
            int n = tc * TN + j;
            float4 r;
            r.x = fmaxf(acc[i][j + 0] + bias[n + 0], 0.f);
            r.y = fmaxf(acc[i][j + 1] + bias[n + 1], 0.f);
            r.z = fmaxf(acc[i][j + 2] + bias[n + 2], 0.f);
            r.w = fmaxf(acc[i][j + 3] + bias[n + 3], 0.f);
            *reinterpret_cast<float4*>(out + (size_t)gm * DIMF + n) = r;
        }
    }
}

// ---------------------------------------------------------------------------
// launch
// ---------------------------------------------------------------------------
extern "C" void kernel_launch(void* const* d_in, const int* in_sizes, int n_in,
                              void* d_out, int out_size) {
    const float* x   = (const float*)d_in[0];
    const int*   ei  = (const int*)d_in[1];
    const float* W1l = (const float*)d_in[2];
    const float* b1l = (const float*)d_in[3];
    const float* W1r = (const float*)d_in[4];
    const float* W2l = (const float*)d_in[5];
    const float* b2l = (const float*)d_in[6];
    const float* W2r = (const float*)d_in[7];
    float* out = (float*)d_out;

    // grids
    const int tot4       = N_NODES * DIMF / 4;                 // 1.28M float4
    const int zero_grid  = (tot4 + 255) / 256;
    const int scat_grid  = (N_EDGES + 7) / 8;                  // 8 warps/block, warp per edge
    const int norm_grid  = (tot4 + 255) / 256;
    const int gemm_grid  = (N_NODES + BM - 1) / BM;            // 313

    static float* p_agg = nullptr;
    static float* p_h   = nullptr;
    if (!p_agg) {
        cudaGetSymbolAddress((void**)&p_agg, g_agg);
        cudaGetSymbolAddress((void**)&p_h,   g_h);
    }

    // ---- layer 1 ----
    zero_kernel<<<zero_grid, 256>>>(1);
    scatter_kernel<<<scat_grid, 256>>>(x, ei, 1);
    normalize_kernel<<<norm_grid, 256>>>();
    gemm_fused_kernel<<<gemm_grid, 256>>>(p_agg, x, W1l, W1r, b1l, p_h);

    // ---- layer 2 ----
    zero_kernel<<<zero_grid, 256>>>(0);
    scatter_kernel<<<scat_grid, 256>>>(p_h, ei, 0);
    normalize_kernel<<<norm_grid, 256>>>();
    gemm_fused_kernel<<<gemm_grid, 256>>>(p_agg, p_h, W2l, W2r, b2l, out);
}

// round 3
// speedup vs baseline: 1.1068x; 1.1068x over previous
#include <cuda_runtime.h>
#include <cuda_bf16.h>
#include <cstdint>

#define N_NODES 40000
#define DIMF    128
#define N_EDGES 640000

// ---- scratch (no allocs allowed) ----
__device__ float g_agg[N_NODES * DIMF];   // neighbor-sum buffer (unnormalized)
__device__ float g_cnt[N_NODES];          // in-degree (float)
__device__ float g_h[N_NODES * DIMF];     // layer-1 output

// ---------------------------------------------------------------------------
// zero agg (+ cnt on first layer)
// ---------------------------------------------------------------------------
__global__ void zero_kernel(int zero_cnt) {
    int i = blockIdx.x * blockDim.x + threadIdx.x;
    const int tot4 = N_NODES * DIMF / 4;
    if (i < tot4) reinterpret_cast<float4*>(g_agg)[i] = make_float4(0.f, 0.f, 0.f, 0.f);
    if (zero_cnt && i < N_NODES) g_cnt[i] = 0.f;
}

// ---------------------------------------------------------------------------
// scatter: one warp per edge; lane moves one float4 (32 x 16B = 512B row).
// red.global.add.v4.f32 — no return trip. edge_index is int32.
// ---------------------------------------------------------------------------
__global__ void scatter_kernel(const float* __restrict__ feat,
                               const int* __restrict__ ei,
                               int do_count) {
    int gw   = blockIdx.x * (blockDim.x >> 5) + (threadIdx.x >> 5);
    int lane = threadIdx.x & 31;
    if (gw >= N_EDGES) return;
    int s = ei[gw];
    int d = ei[N_EDGES + gw];
    if ((unsigned)s >= N_NODES || (unsigned)d >= N_NODES) return;

    float4 v = reinterpret_cast<const float4*>(feat + (size_t)s * DIMF)[lane];
    float* p = g_agg + (size_t)d * DIMF + lane * 4;
    asm volatile("red.global.add.v4.f32 [%0], {%1, %2, %3, %4};"
                 :: "l"(p), "f"(v.x), "f"(v.y), "f"(v.z), "f"(v.w)
                 : "memory");
    if (do_count && lane == 0) {
        atomicAdd(&g_cnt[d], 1.0f);
    }
}

// ---------------------------------------------------------------------------
// fused SAGE GEMM with on-the-fly mean normalization:
//   out[m][n] = relu( (1/max(cnt[m],1)) * sum_k A0[m][k]*W0[n][k]
//                    + sum_k A1[m][k]*W1[n][k] + bias[n] )
// NT gemm, M=40000, N=128, K=128 (x2 mats). BM=BN=128, BK=16, 256 thr,
// 8x8 micro-tile, float4 LDG/LDS, register-prefetched tiles.
// ---------------------------------------------------------------------------
#define BM 128
#define BN 128
#define BK 16
#define LDP (BM + 4)   // padded smem row (floats): stride 132, 16B-aligned

__global__ __launch_bounds__(256, 2) void gemm_fused_kernel(
        const float* __restrict__ A0, const float* __restrict__ A1,
        const float* __restrict__ cnt,
        const float* __restrict__ W0, const float* __restrict__ W1,
        const float* __restrict__ bias, float* __restrict__ out) {
    __shared__ float As[BK * LDP];
    __shared__ float Bs[BK * LDP];

    const int tid = threadIdx.x;
    const int m0  = blockIdx.x * BM;
    const int tr  = tid >> 4;     // 0..15
    const int tc  = tid & 15;     // 0..15

    // tile-load coords: thread handles rows r0, r1 (= r0+64) at k-quad q
    const int r0 = tid >> 2;           // 0..63
    const int r1 = r0 + 64;            // 64..127
    const int q  = tid & 3;            // 0..3 (16B chunk within BK)

    // mean scale for the two A rows this thread loads (A0 operand only)
    const int gm0 = m0 + r0, gm1 = m0 + r1;
    const float s0 = (gm0 < N_NODES) ? __frcp_rn(fmaxf(__ldg(&cnt[gm0]), 1.f)) : 0.f;
    const float s1 = (gm1 < N_NODES) ? __frcp_rn(fmaxf(__ldg(&cnt[gm1]), 1.f)) : 0.f;

    float acc[8][8];
#pragma unroll
    for (int i = 0; i < 8; ++i)
#pragma unroll
        for (int j = 0; j < 8; ++j) acc[i][j] = 0.f;

    const float4 f4z = make_float4(0.f, 0.f, 0.f, 0.f);
    float4 a0r, a1r, b0r, b1r;

    // ---- tile loader (kt in [0,16): kt<8 -> A0/W0 scaled, else A1/W1) ----
    auto load_tile = [&](int kt, float4& av0, float4& av1, float4& bv0, float4& bv1) {
        const float* A = (kt < 8) ? A0 : A1;
        const float* W = (kt < 8) ? W0 : W1;
        const float sc0 = (kt < 8) ? s0 : 1.f;
        const float sc1 = (kt < 8) ? s1 : 1.f;
        const int k0 = (kt & 7) * BK + q * 4;
        av0 = (gm0 < N_NODES) ? *reinterpret_cast<const float4*>(A + (size_t)gm0 * DIMF + k0) : f4z;
        av1 = (gm1 < N_NODES) ? *reinterpret_cast<const float4*>(A + (size_t)gm1 * DIMF + k0) : f4z;
        av0.x *= sc0; av0.y *= sc0; av0.z *= sc0; av0.w *= sc0;
        av1.x *= sc1; av1.y *= sc1; av1.z *= sc1; av1.w *= sc1;
        bv0 = *reinterpret_cast<const float4*>(W + (size_t)r0 * DIMF + k0);
        bv1 = *reinterpret_cast<const float4*>(W + (size_t)r1 * DIMF + k0);
    };

    load_tile(0, a0r, a1r, b0r, b1r);

#pragma unroll 1
    for (int kt = 0; kt < 16; ++kt) {
        __syncthreads();   // previous compute done; smem free
        // transposed STS: As[k][m]
        const int kb = q * 4;
        As[(kb + 0) * LDP + r0] = a0r.x;  As[(kb + 1) * LDP + r0] = a0r.y;
        As[(kb + 2) * LDP + r0] = a0r.z;  As[(kb + 3) * LDP + r0] = a0r.w;
        As[(kb + 0) * LDP + r1] = a1r.x;  As[(kb + 1) * LDP + r1] = a1r.y;
        As[(kb + 2) * LDP + r1] = a1r.z;  As[(kb + 3) * LDP + r1] = a1r.w;
        Bs[(kb + 0) * LDP + r0] = b0r.x;  Bs[(kb + 1) * LDP + r0] = b0r.y;
        Bs[(kb + 2) * LDP + r0] = b0r.z;  Bs[(kb + 3) * LDP + r0] = b0r.w;
        Bs[(kb + 0) * LDP + r1] = b1r.x;  Bs[(kb + 1) * LDP + r1] = b1r.y;
        Bs[(kb + 2) * LDP + r1] = b1r.z;  Bs[(kb + 3) * LDP + r1] = b1r.w;
        __syncthreads();

        if (kt < 15) load_tile(kt + 1, a0r, a1r, b0r, b1r);  // hide LDG under compute

#pragma unroll
        for (int k = 0; k < BK; ++k) {
            float4 aA = *reinterpret_cast<const float4*>(&As[k * LDP + tr * 8]);
            float4 aB = *reinterpret_cast<const float4*>(&As[k * LDP + tr * 8 + 4]);
            float4 bA = *reinterpret_cast<const float4*>(&Bs[k * LDP + tc * 8]);
            float4 bB = *reinterpret_cast<const float4*>(&Bs[k * LDP + tc * 8 + 4]);
            float a[8] = {aA.x, aA.y, aA.z, aA.w, aB.x, aB.y, aB.z, aB.w};
            float b[8] = {bA.x, bA.y, bA.z, bA.w, bB.x, bB.y, bB.z, bB.w};
#pragma unroll
            for (int i = 0; i < 8; ++i)
#pragma unroll
                for (int j = 0; j < 8; ++j) acc[i][j] += a[i] * b[j];
        }
    }

    // epilogue: + bias, relu (bias cached via __ldg, L1-resident)
    float bv[8];
#pragma unroll
    for (int j = 0; j < 8; ++j) bv[j] = __ldg(&bias[tc * 8 + j]);

#pragma unroll
    for (int i = 0; i < 8; ++i) {
        int gm = m0 + tr * 8 + i;
        if (gm >= N_NODES) continue;
#pragma unroll
        for (int j = 0; j < 8; j += 4) {
            int n = tc * 8 + j;
            float4 r;
            r.x = fmaxf(acc[i][j + 0] + bv[j + 0], 0.f);
            r.y = fmaxf(acc[i][j + 1] + bv[j + 1], 0.f);
            r.z = fmaxf(acc[i][j + 2] + bv[j + 2], 0.f);
            r.w = fmaxf(acc[i][j + 3] + bv[j + 3], 0.f);
            *reinterpret_cast<float4*>(out + (size_t)gm * DIMF + n) = r;
        }
    }
}

// ---------------------------------------------------------------------------
// launch
// ---------------------------------------------------------------------------
extern "C" void kernel_launch(void* const* d_in, const int* in_sizes, int n_in,
                              void* d_out, int out_size) {
    const float* x   = (const float*)d_in[0];
    const int*   ei  = (const int*)d_in[1];
    const float* W1l = (const float*)d_in[2];
    const float* b1l = (const float*)d_in[3];
    const float* W1r = (const float*)d_in[4];
    const float* W2l = (const float*)d_in[5];
    const float* b2l = (const float*)d_in[6];
    const float* W2r = (const float*)d_in[7];
    float* out = (float*)d_out;

    const int tot4      = N_NODES * DIMF / 4;
    const int zero_grid = (tot4 + 255) / 256;
    const int scat_grid = (N_EDGES + 7) / 8;              // 8 warps/block, warp/edge
    const int gemm_grid = (N_NODES + BM - 1) / BM;        // 313

    static float* p_agg = nullptr;
    static float* p_h   = nullptr;
    static float* p_cnt = nullptr;
    if (!p_agg) {
        cudaGetSymbolAddress((void**)&p_agg, g_agg);
        cudaGetSymbolAddress((void**)&p_h,   g_h);
        cudaGetSymbolAddress((void**)&p_cnt, g_cnt);
    }

    // ---- layer 1 ----
    zero_kernel<<<zero_grid, 256>>>(1);
    scatter_kernel<<<scat_grid, 256>>>(x, ei, 1);
    gemm_fused_kernel<<<gemm_grid, 256>>>(p_agg, x, p_cnt, W1l, W1r, b1l, p_h);

    // ---- layer 2 ----
    zero_kernel<<<zero_grid, 256>>>(0);
    scatter_kernel<<<scat_grid, 256>>>(p_h, ei, 0);
    gemm_fused_kernel<<<gemm_grid, 256>>>(p_agg, p_h, p_cnt, W2l, W2r, b2l, out);
}

// round 4
// speedup vs baseline: 1.5231x; 1.3762x over previous
#include <cuda_runtime.h>
#include <cuda_bf16.h>
#include <cstdint>

#define N_NODES 40000
#define DIMF    128
#define N_EDGES 640000

// ---- scratch (no allocs allowed) ----
__device__ float g_agg[N_NODES * DIMF];   // neighbor-sum buffer (unnormalized)
__device__ float g_cnt[N_NODES];          // in-degree (float)
__device__ float g_h[N_NODES * DIMF];     // layer-1 output

// ---------------------------------------------------------------------------
// zero agg + cnt (layer 1 only; layer-2 zeroing is fused into GEMM1 epilogue)
// ---------------------------------------------------------------------------
__global__ void zero_kernel() {
    int i = blockIdx.x * blockDim.x + threadIdx.x;
    const int tot4 = N_NODES * DIMF / 4;
    if (i < tot4) reinterpret_cast<float4*>(g_agg)[i] = make_float4(0.f, 0.f, 0.f, 0.f);
    if (i < N_NODES) g_cnt[i] = 0.f;
}

// ---------------------------------------------------------------------------
// scatter: one warp per edge; lane moves one float4 (32 x 16B = 512B row).
// red.global.add.v4.f32 — no return trip. edge_index is int32.
// ---------------------------------------------------------------------------
__global__ void scatter_kernel(const float* __restrict__ feat,
                               const int* __restrict__ ei,
                               int do_count) {
    int gw   = blockIdx.x * (blockDim.x >> 5) + (threadIdx.x >> 5);
    int lane = threadIdx.x & 31;
    if (gw >= N_EDGES) return;
    int s = ei[gw];
    int d = ei[N_EDGES + gw];
    if ((unsigned)s >= N_NODES || (unsigned)d >= N_NODES) return;

    float4 v = reinterpret_cast<const float4*>(feat + (size_t)s * DIMF)[lane];
    float* p = g_agg + (size_t)d * DIMF + lane * 4;
    asm volatile("red.global.add.v4.f32 [%0], {%1, %2, %3, %4};"
                 :: "l"(p), "f"(v.x), "f"(v.y), "f"(v.z), "f"(v.w)
                 : "memory");
    if (do_count && lane == 0) {
        atomicAdd(&g_cnt[d], 1.0f);
    }
}

// ---------------------------------------------------------------------------
// Tensor-core (tf32 mma.sync) fused SAGE GEMM with on-the-fly mean norm:
//   out[m][n] = relu( (1/max(cnt[m],1)) * sum_k A0[m][k]*W0[n][k]
//                    + sum_k A1[m][k]*W1[n][k] + bias[n] )
// BM=128, BN=128(all of N), BK=16, logical K=256 (two mats).
// 256 thr = 8 warps in 2(M)x4(N); warp tile 64x32; m16n8k8 tf32 MMA.
// If zero_buf != null, epilogue zero-fills zero_buf rows [m0, m0+BM)
// (safe: each block is the only reader of its own A0 rows).
// ---------------------------------------------------------------------------
#define BM 128
#define BK 16
#define LDP 132   // padded smem row stride (uint32 elems)

__device__ __forceinline__ uint32_t f2tf32(float v) {
    uint32_t t;
    asm("cvt.rna.tf32.f32 %0, %1;" : "=r"(t) : "f"(v));
    return t;
}

__global__ __launch_bounds__(256, 2) void gemm_tc_kernel(
        const float* A0, const float* __restrict__ A1,
        const float* __restrict__ cnt,
        const float* __restrict__ W0, const float* __restrict__ W1,
        const float* __restrict__ bias, float* __restrict__ out,
        float* zero_buf) {
    __shared__ uint32_t As[BK * LDP];
    __shared__ uint32_t Bs[BK * LDP];

    const int tid   = threadIdx.x;
    const int m0    = blockIdx.x * BM;
    const int lane  = tid & 31;
    const int warp  = tid >> 5;
    const int warpM = warp & 1;        // 0..1 -> 64 rows each
    const int warpN = warp >> 1;       // 0..3 -> 32 cols each
    const int lr    = lane >> 2;       // 0..7
    const int lc    = lane & 3;        // 0..3

    // tile-load coords: thread stages rows r0, r1 (=r0+64) at 16B k-chunk q
    const int r0 = tid >> 2;           // 0..63
    const int r1 = r0 + 64;            // 64..127
    const int q  = tid & 3;            // 0..3

    const int gm0 = m0 + r0, gm1 = m0 + r1;
    const float s0 = (gm0 < N_NODES) ? __frcp_rn(fmaxf(__ldg(&cnt[gm0]), 1.f)) : 0.f;
    const float s1 = (gm1 < N_NODES) ? __frcp_rn(fmaxf(__ldg(&cnt[gm1]), 1.f)) : 0.f;

    float acc[4][4][4];   // [m-tile][n-tile][frag]
#pragma unroll
    for (int i = 0; i < 4; ++i)
#pragma unroll
        for (int j = 0; j < 4; ++j)
#pragma unroll
            for (int f = 0; f < 4; ++f) acc[i][j][f] = 0.f;

    const float4 f4z = make_float4(0.f, 0.f, 0.f, 0.f);
    float4 a0r, a1r, b0r, b1r;

    auto load_tile = [&](int kt, float4& av0, float4& av1, float4& bv0, float4& bv1) {
        const float* A = (kt < 8) ? A0 : A1;
        const float* W = (kt < 8) ? W0 : W1;
        const float sc0 = (kt < 8) ? s0 : 1.f;
        const float sc1 = (kt < 8) ? s1 : 1.f;
        const int k0 = (kt & 7) * BK + q * 4;
        av0 = (gm0 < N_NODES) ? *reinterpret_cast<const float4*>(A + (size_t)gm0 * DIMF + k0) : f4z;
        av1 = (gm1 < N_NODES) ? *reinterpret_cast<const float4*>(A + (size_t)gm1 * DIMF + k0) : f4z;
        av0.x *= sc0; av0.y *= sc0; av0.z *= sc0; av0.w *= sc0;
        av1.x *= sc1; av1.y *= sc1; av1.z *= sc1; av1.w *= sc1;
        bv0 = *reinterpret_cast<const float4*>(W + (size_t)r0 * DIMF + k0);   // W rows 0..127
        bv1 = *reinterpret_cast<const float4*>(W + (size_t)r1 * DIMF + k0);
    };

    load_tile(0, a0r, a1r, b0r, b1r);

#pragma unroll 1
    for (int kt = 0; kt < 16; ++kt) {
        __syncthreads();
        const int kb = q * 4;
        // transposed STS, tf32-converted: As[k][m], Bs[k][n]
        As[(kb + 0) * LDP + r0] = f2tf32(a0r.x);  As[(kb + 1) * LDP + r0] = f2tf32(a0r.y);
        As[(kb + 2) * LDP + r0] = f2tf32(a0r.z);  As[(kb + 3) * LDP + r0] = f2tf32(a0r.w);
        As[(kb + 0) * LDP + r1] = f2tf32(a1r.x);  As[(kb + 1) * LDP + r1] = f2tf32(a1r.y);
        As[(kb + 2) * LDP + r1] = f2tf32(a1r.z);  As[(kb + 3) * LDP + r1] = f2tf32(a1r.w);
        Bs[(kb + 0) * LDP + r0] = f2tf32(b0r.x);  Bs[(kb + 1) * LDP + r0] = f2tf32(b0r.y);
        Bs[(kb + 2) * LDP + r0] = f2tf32(b0r.z);  Bs[(kb + 3) * LDP + r0] = f2tf32(b0r.w);
        Bs[(kb + 0) * LDP + r1] = f2tf32(b1r.x);  Bs[(kb + 1) * LDP + r1] = f2tf32(b1r.y);
        Bs[(kb + 2) * LDP + r1] = f2tf32(b1r.z);  Bs[(kb + 3) * LDP + r1] = f2tf32(b1r.w);
        __syncthreads();

        if (kt < 15) load_tile(kt + 1, a0r, a1r, b0r, b1r);   // hide LDG under MMA

#pragma unroll
        for (int s = 0; s < BK; s += 8) {
            // B fragments for the 4 n-tiles
            uint32_t bf0[4], bf1[4];
#pragma unroll
            for (int nt = 0; nt < 4; ++nt) {
                const int n = warpN * 32 + nt * 8 + lr;
                bf0[nt] = Bs[(s + lc) * LDP + n];
                bf1[nt] = Bs[(s + lc + 4) * LDP + n];
            }
#pragma unroll
            for (int mt = 0; mt < 4; ++mt) {
                const int m = warpM * 64 + mt * 16 + lr;
                uint32_t a0 = As[(s + lc) * LDP + m];
                uint32_t a1 = As[(s + lc) * LDP + m + 8];
                uint32_t a2 = As[(s + lc + 4) * LDP + m];
                uint32_t a3 = As[(s + lc + 4) * LDP + m + 8];
#pragma unroll
                for (int nt = 0; nt < 4; ++nt) {
                    asm volatile(
                        "mma.sync.aligned.m16n8k8.row.col.f32.tf32.tf32.f32 "
                        "{%0,%1,%2,%3}, {%4,%5,%6,%7}, {%8,%9}, {%0,%1,%2,%3};"
                        : "+f"(acc[mt][nt][0]), "+f"(acc[mt][nt][1]),
                          "+f"(acc[mt][nt][2]), "+f"(acc[mt][nt][3])
                        : "r"(a0), "r"(a1), "r"(a2), "r"(a3),
                          "r"(bf0[nt]), "r"(bf1[nt]));
                }
            }
        }
    }

    // epilogue: + bias, relu; c-frag mapping rows lr/lr+8, cols 2*lc(+1)
#pragma unroll
    for (int nt = 0; nt < 4; ++nt) {
        const int n = warpN * 32 + nt * 8 + 2 * lc;
        const float bv0 = __ldg(&bias[n]);
        const float bv1 = __ldg(&bias[n + 1]);
#pragma unroll
        for (int mt = 0; mt < 4; ++mt) {
            const int r = m0 + warpM * 64 + mt * 16 + lr;
            if (r < N_NODES) {
                float2 v;
                v.x = fmaxf(acc[mt][nt][0] + bv0, 0.f);
                v.y = fmaxf(acc[mt][nt][1] + bv1, 0.f);
                *reinterpret_cast<float2*>(out + (size_t)r * DIMF + n) = v;
            }
            if (r + 8 < N_NODES) {
                float2 v;
                v.x = fmaxf(acc[mt][nt][2] + bv0, 0.f);
                v.y = fmaxf(acc[mt][nt][3] + bv1, 0.f);
                *reinterpret_cast<float2*>(out + (size_t)(r + 8) * DIMF + n) = v;
            }
        }
    }

    // fused zeroing of this block's agg rows for the next layer
    if (zero_buf) {
        const float4 z = make_float4(0.f, 0.f, 0.f, 0.f);
#pragma unroll
        for (int i = 0; i < 16; ++i) {
            int e   = tid + i * 256;            // float4 index within [BM x 128]
            int row = m0 + (e >> 5);
            if (row < N_NODES)
                reinterpret_cast<float4*>(zero_buf + (size_t)row * DIMF)[e & 31] = z;
        }
    }
}

// ---------------------------------------------------------------------------
// launch
// ---------------------------------------------------------------------------
extern "C" void kernel_launch(void* const* d_in, const int* in_sizes, int n_in,
                              void* d_out, int out_size) {
    const float* x   = (const float*)d_in[0];
    const int*   ei  = (const int*)d_in[1];
    const float* W1l = (const float*)d_in[2];
    const float* b1l = (const float*)d_in[3];
    const float* W1r = (const float*)d_in[4];
    const float* W2l = (const float*)d_in[5];
    const float* b2l = (const float*)d_in[6];
    const float* W2r = (const float*)d_in[7];
    float* out = (float*)d_out;

    const int tot4      = N_NODES * DIMF / 4;
    const int zero_grid = (tot4 + 255) / 256;
    const int scat_grid = (N_EDGES + 7) / 8;              // 8 warps/block, warp/edge
    const int gemm_grid = (N_NODES + BM - 1) / BM;        // 313

    static float* p_agg = nullptr;
    static float* p_h   = nullptr;
    static float* p_cnt = nullptr;
    if (!p_agg) {
        cudaGetSymbolAddress((void**)&p_agg, g_agg);
        cudaGetSymbolAddress((void**)&p_h,   g_h);
        cudaGetSymbolAddress((void**)&p_cnt, g_cnt);
    }

    // ---- layer 1 ----
    zero_kernel<<<zero_grid, 256>>>();
    scatter_kernel<<<scat_grid, 256>>>(x, ei, 1);
    gemm_tc_kernel<<<gemm_grid, 256>>>(p_agg, x, p_cnt, W1l, W1r, b1l, p_h, p_agg);

    // ---- layer 2 ----
    scatter_kernel<<<scat_grid, 256>>>(p_h, ei, 0);
    gemm_tc_kernel<<<gemm_grid, 256>>>(p_agg, p_h, p_cnt, W2l, W2r, b2l, out, nullptr);
}

// round 5
// speedup vs baseline: 1.6531x; 1.0853x over previous
#include <cuda_runtime.h>
#include <cuda_bf16.h>
#include <cstdint>

#define N_NODES 40000
#define DIMF    128
#define N_EDGES 640000
#define EPW     16            // edges per warp

// ---- scratch (no allocs allowed) ----
__device__ float g_agg[N_NODES * DIMF];   // neighbor-sum buffer (unnormalized)
__device__ float g_cnt[N_NODES];          // in-degree (float)
__device__ float g_h[N_NODES * DIMF];     // layer-1 output

// ---------------------------------------------------------------------------
// zero agg + cnt (layer 1 only; layer-2 zeroing is fused into GEMM1 epilogue)
// ---------------------------------------------------------------------------
__global__ void zero_kernel() {
    int i = blockIdx.x * blockDim.x + threadIdx.x;
    const int tot4 = N_NODES * DIMF / 4;
    if (i < tot4) reinterpret_cast<float4*>(g_agg)[i] = make_float4(0.f, 0.f, 0.f, 0.f);
    if (i < N_NODES) g_cnt[i] = 0.f;
}

// ---------------------------------------------------------------------------
// scatter: EPW edges per warp. Lanes 0..15 fetch the 16 src indices, lanes
// 16..31 the 16 dst indices (2 coalesced LDG per warp per 16 edges), shfl-
// broadcast, then 16 independent gather(LDG.128/lane) -> red.v4 chains (MLP=16).
// ---------------------------------------------------------------------------
__global__ __launch_bounds__(256) void scatter_kernel(
        const float* __restrict__ feat,
        const int* __restrict__ ei,
        int do_count) {
    const int wid  = blockIdx.x * (blockDim.x >> 5) + (threadIdx.x >> 5);
    const int lane = threadIdx.x & 31;
    const int base = wid * EPW;
    if (base >= N_EDGES) return;

    // lanes 0..15: src[base+lane]; lanes 16..31: dst[base+lane-16]
    const int nrem = min(EPW, N_EDGES - base);
    int idx = -1;
    const int off = lane & 15;
    if (off < nrem)
        idx = ei[(lane < 16 ? base : N_EDGES + base) + off];

    // degree counts: one atomic per dst lane
    if (do_count && lane >= 16 && (unsigned)idx < N_NODES)
        atomicAdd(&g_cnt[idx], 1.0f);

#pragma unroll
    for (int j = 0; j < EPW; ++j) {
        int s = __shfl_sync(0xffffffffu, idx, j);
        int d = __shfl_sync(0xffffffffu, idx, 16 + j);
        if ((unsigned)s >= N_NODES || (unsigned)d >= N_NODES) continue;
        float4 v = reinterpret_cast<const float4*>(feat + (size_t)s * DIMF)[lane];
        float* p = g_agg + (size_t)d * DIMF + lane * 4;
        asm volatile("red.global.add.v4.f32 [%0], {%1, %2, %3, %4};"
                     :: "l"(p), "f"(v.x), "f"(v.y), "f"(v.z), "f"(v.w)
                     : "memory");
    }
}

// ---------------------------------------------------------------------------
// Tensor-core (tf32 mma.sync) fused SAGE GEMM with on-the-fly mean norm:
//   out[m][n] = relu( (1/max(cnt[m],1)) * sum_k A0[m][k]*W0[n][k]
//                    + sum_k A1[m][k]*W1[n][k] + bias[n] )
// BM=128, BN=128(all of N), BK=16, logical K=256 (two mats).
// 256 thr = 8 warps in 2(M)x4(N); warp tile 64x32; m16n8k8 tf32 MMA.
// If zero_buf != null, epilogue zero-fills zero_buf rows [m0, m0+BM).
// ---------------------------------------------------------------------------
#define BM 128
#define BK 16
#define LDP 132   // padded smem row stride (uint32 elems)

__device__ __forceinline__ uint32_t f2tf32(float v) {
    uint32_t t;
    asm("cvt.rna.tf32.f32 %0, %1;" : "=r"(t) : "f"(v));
    return t;
}

__global__ __launch_bounds__(256, 2) void gemm_tc_kernel(
        const float* A0, const float* __restrict__ A1,
        const float* __restrict__ cnt,
        const float* __restrict__ W0, const float* __restrict__ W1,
        const float* __restrict__ bias, float* __restrict__ out,
        float* zero_buf) {
    __shared__ uint32_t As[BK * LDP];
    __shared__ uint32_t Bs[BK * LDP];

    const int tid   = threadIdx.x;
    const int m0    = blockIdx.x * BM;
    const int lane  = tid & 31;
    const int warp  = tid >> 5;
    const int warpM = warp & 1;        // 0..1 -> 64 rows each
    const int warpN = warp >> 1;       // 0..3 -> 32 cols each
    const int lr    = lane >> 2;       // 0..7
    const int lc    = lane & 3;        // 0..3

    const int r0 = tid >> 2;           // 0..63
    const int r1 = r0 + 64;            // 64..127
    const int q  = tid & 3;            // 0..3

    const int gm0 = m0 + r0, gm1 = m0 + r1;
    const float s0 = (gm0 < N_NODES) ? __frcp_rn(fmaxf(__ldg(&cnt[gm0]), 1.f)) : 0.f;
    const float s1 = (gm1 < N_NODES) ? __frcp_rn(fmaxf(__ldg(&cnt[gm1]), 1.f)) : 0.f;

    float acc[4][4][4];   // [m-tile][n-tile][frag]
#pragma unroll
    for (int i = 0; i < 4; ++i)
#pragma unroll
        for (int j = 0; j < 4; ++j)
#pragma unroll
            for (int f = 0; f < 4; ++f) acc[i][j][f] = 0.f;

    const float4 f4z = make_float4(0.f, 0.f, 0.f, 0.f);
    float4 a0r, a1r, b0r, b1r;

    auto load_tile = [&](int kt, float4& av0, float4& av1, float4& bv0, float4& bv1) {
        const float* A = (kt < 8) ? A0 : A1;
        const float* W = (kt < 8) ? W0 : W1;
        const float sc0 = (kt < 8) ? s0 : 1.f;
        const float sc1 = (kt < 8) ? s1 : 1.f;
        const int k0 = (kt & 7) * BK + q * 4;
        av0 = (gm0 < N_NODES) ? *reinterpret_cast<const float4*>(A + (size_t)gm0 * DIMF + k0) : f4z;
        av1 = (gm1 < N_NODES) ? *reinterpret_cast<const float4*>(A + (size_t)gm1 * DIMF + k0) : f4z;
        av0.x *= sc0; av0.y *= sc0; av0.z *= sc0; av0.w *= sc0;
        av1.x *= sc1; av1.y *= sc1; av1.z *= sc1; av1.w *= sc1;
        bv0 = *reinterpret_cast<const float4*>(W + (size_t)r0 * DIMF + k0);
        bv1 = *reinterpret_cast<const float4*>(W + (size_t)r1 * DIMF + k0);
    };

    load_tile(0, a0r, a1r, b0r, b1r);

#pragma unroll 1
    for (int kt = 0; kt < 16; ++kt) {
        __syncthreads();
        const int kb = q * 4;
        As[(kb + 0) * LDP + r0] = f2tf32(a0r.x);  As[(kb + 1) * LDP + r0] = f2tf32(a0r.y);
        As[(kb + 2) * LDP + r0] = f2tf32(a0r.z);  As[(kb + 3) * LDP + r0] = f2tf32(a0r.w);
        As[(kb + 0) * LDP + r1] = f2tf32(a1r.x);  As[(kb + 1) * LDP + r1] = f2tf32(a1r.y);
        As[(kb + 2) * LDP + r1] = f2tf32(a1r.z);  As[(kb + 3) * LDP + r1] = f2tf32(a1r.w);
        Bs[(kb + 0) * LDP + r0] = f2tf32(b0r.x);  Bs[(kb + 1) * LDP + r0] = f2tf32(b0r.y);
        Bs[(kb + 2) * LDP + r0] = f2tf32(b0r.z);  Bs[(kb + 3) * LDP + r0] = f2tf32(b0r.w);
        Bs[(kb + 0) * LDP + r1] = f2tf32(b1r.x);  Bs[(kb + 1) * LDP + r1] = f2tf32(b1r.y);
        Bs[(kb + 2) * LDP + r1] = f2tf32(b1r.z);  Bs[(kb + 3) * LDP + r1] = f2tf32(b1r.w);
        __syncthreads();

        if (kt < 15) load_tile(kt + 1, a0r, a1r, b0r, b1r);   // hide LDG under MMA

#pragma unroll
        for (int s = 0; s < BK; s += 8) {
            uint32_t bf0[4], bf1[4];
#pragma unroll
            for (int nt = 0; nt < 4; ++nt) {
                const int n = warpN * 32 + nt * 8 + lr;
                bf0[nt] = Bs[(s + lc) * LDP + n];
                bf1[nt] = Bs[(s + lc + 4) * LDP + n];
            }
#pragma unroll
            for (int mt = 0; mt < 4; ++mt) {
                const int m = warpM * 64 + mt * 16 + lr;
                uint32_t a0 = As[(s + lc) * LDP + m];
                uint32_t a1 = As[(s + lc) * LDP + m + 8];
                uint32_t a2 = As[(s + lc + 4) * LDP + m];
                uint32_t a3 = As[(s + lc + 4) * LDP + m + 8];
#pragma unroll
                for (int nt = 0; nt < 4; ++nt) {
                    asm volatile(
                        "mma.sync.aligned.m16n8k8.row.col.f32.tf32.tf32.f32 "
                        "{%0,%1,%2,%3}, {%4,%5,%6,%7}, {%8,%9}, {%0,%1,%2,%3};"
                        : "+f"(acc[mt][nt][0]), "+f"(acc[mt][nt][1]),
                          "+f"(acc[mt][nt][2]), "+f"(acc[mt][nt][3])
                        : "r"(a0), "r"(a1), "r"(a2), "r"(a3),
                          "r"(bf0[nt]), "r"(bf1[nt]));
                }
            }
        }
    }

    // epilogue: + bias, relu
#pragma unroll
    for (int nt = 0; nt < 4; ++nt) {
        const int n = warpN * 32 + nt * 8 + 2 * lc;
        const float bv0 = __ldg(&bias[n]);
        const float bv1 = __ldg(&bias[n + 1]);
#pragma unroll
        for (int mt = 0; mt < 4; ++mt) {
            const int r = m0 + warpM * 64 + mt * 16 + lr;
            if (r < N_NODES) {
                float2 v;
                v.x = fmaxf(acc[mt][nt][0] + bv0, 0.f);
                v.y = fmaxf(acc[mt][nt][1] + bv1, 0.f);
                *reinterpret_cast<float2*>(out + (size_t)r * DIMF + n) = v;
            }
            if (r + 8 < N_NODES) {
                float2 v;
                v.x = fmaxf(acc[mt][nt][2] + bv0, 0.f);
                v.y = fmaxf(acc[mt][nt][3] + bv1, 0.f);
                *reinterpret_cast<float2*>(out + (size_t)(r + 8) * DIMF + n) = v;
            }
        }
    }

    // fused zeroing of this block's agg rows for the next layer
    if (zero_buf) {
        const float4 z = make_float4(0.f, 0.f, 0.f, 0.f);
#pragma unroll
        for (int i = 0; i < 16; ++i) {
            int e   = tid + i * 256;
            int row = m0 + (e >> 5);
            if (row < N_NODES)
                reinterpret_cast<float4*>(zero_buf + (size_t)row * DIMF)[e & 31] = z;
        }
    }
}

// ---------------------------------------------------------------------------
// launch
// ---------------------------------------------------------------------------
extern "C" void kernel_launch(void* const* d_in, const int* in_sizes, int n_in,
                              void* d_out, int out_size) {
    const float* x   = (const float*)d_in[0];
    const int*   ei  = (const int*)d_in[1];
    const float* W1l = (const float*)d_in[2];
    const float* b1l = (const float*)d_in[3];
    const float* W1r = (const float*)d_in[4];
    const float* W2l = (const float*)d_in[5];
    const float* b2l = (const float*)d_in[6];
    const float* W2r = (const float*)d_in[7];
    float* out = (float*)d_out;

    const int tot4      = N_NODES * DIMF / 4;
    const int zero_grid = (tot4 + 255) / 256;
    const int n_warps   = (N_EDGES + EPW - 1) / EPW;      // 40000 warps
    const int scat_grid = (n_warps + 7) / 8;              // 5000 blocks of 8 warps
    const int gemm_grid = (N_NODES + BM - 1) / BM;        // 313

    static float* p_agg = nullptr;
    static float* p_h   = nullptr;
    static float* p_cnt = nullptr;
    if (!p_agg) {
        cudaGetSymbolAddress((void**)&p_agg, g_agg);
        cudaGetSymbolAddress((void**)&p_h,   g_h);
        cudaGetSymbolAddress((void**)&p_cnt, g_cnt);
    }

    // ---- layer 1 ----
    zero_kernel<<<zero_grid, 256>>>();
    scatter_kernel<<<scat_grid, 256>>>(x, ei, 1);
    gemm_tc_kernel<<<gemm_grid, 256>>>(p_agg, x, p_cnt, W1l, W1r, b1l, p_h, p_agg);

    // ---- layer 2 ----
    scatter_kernel<<<scat_grid, 256>>>(p_h, ei, 0);
    gemm_tc_kernel<<<gemm_grid, 256>>>(p_agg, p_h, p_cnt, W2l, W2r, b2l, out, nullptr);
}